// round 6
// baseline (speedup 1.0000x reference)
#include <cuda_runtime.h>

// HMM forward for CgpHmmCell (nCodons=2): 24 states, batch=2048, T=2000.
// One thread per sequence, 64 warps. Beta-rescaled states; fast log/rcp;
// E-rows double-buffered one 4-step block ahead (ping-pong pair loop).

#define T_LEN 2000
#define BATCH 2048

__device__ float g_coef[17];
__device__ float g_raw[6];
__device__ float g_pi[24];
__device__ float g_Bst[64 * 20];

// ---------------------------------------------------------------------------
// Setup kernel (identical to R3/R5)
// ---------------------------------------------------------------------------
__global__ void setup_kernel(const float* __restrict__ w,
                             const float* __restrict__ ew,
                             const float* __restrict__ ik) {
    int tid = threadIdx.x;
    if (tid == 0) {
        float w12 = w[12];
        float d1 = 1.0f - w12 * w12;
        float d2 = 1.0f - w12 * w12 * w12;
        float a00, a01, a34, a314, a37, a310, a67, a617, a610,
              a920, a910, a164, a1614, a197, a1917, a2210, a2220;
        {
            float v0 = 1.0f - w[0], v1 = w[0];
            float m = fmaxf(v0, v1);
            float e0 = expf(v0 - m), e1 = expf(v1 - m);
            float s = e0 + e1;
            a00 = e0 / s; a01 = e1 / s;
        }
        {
            float v0 = w[1], v1 = w[3], v2 = d1, v3 = d2;
            float m = fmaxf(fmaxf(v0, v1), fmaxf(v2, v3));
            float e0 = expf(v0 - m), e1 = expf(v1 - m), e2 = expf(v2 - m), e3 = expf(v3 - m);
            float s = e0 + e1 + e2 + e3;
            a34 = e0 / s; a314 = e1 / s; a37 = e2 / s; a310 = e3 / s;
        }
        {
            float v0 = w[2], v1 = w[4], v2 = d1;
            float m = fmaxf(fmaxf(v0, v1), v2);
            float e0 = expf(v0 - m), e1 = expf(v1 - m), e2 = expf(v2 - m);
            float s = e0 + e1 + e2;
            a67 = e0 / s; a617 = e1 / s; a610 = e2 / s;
        }
        {
            float v0 = w[5], v1 = 1.0f - w[5];
            float m = fmaxf(v0, v1);
            float e0 = expf(v0 - m), e1 = expf(v1 - m);
            float s = e0 + e1;
            a920 = e0 / s; a910 = e1 / s;
        }
        {
            float v0 = w[6], v1 = 1.0f - w[9];
            float m = fmaxf(v0, v1);
            float e0 = expf(v0 - m), e1 = expf(v1 - m);
            float s = e0 + e1;
            a164 = e0 / s; a1614 = e1 / s;
        }
        {
            float v0 = w[7], v1 = 1.0f - w[10];
            float m = fmaxf(v0, v1);
            float e0 = expf(v0 - m), e1 = expf(v1 - m);
            float s = e0 + e1;
            a197 = e0 / s; a1917 = e1 / s;
        }
        {
            float v0 = w[8], v1 = 1.0f - w[11];
            float m = fmaxf(v0, v1);
            float e0 = expf(v0 - m), e1 = expf(v1 - m);
            float s = e0 + e1;
            a2210 = e0 / s; a2220 = e1 / s;
        }
        const float S6 = 1.0f / 6.0f, S36 = 1.0f / 36.0f, S216 = 1.0f / 216.0f;
        g_coef[0]  = a00;          g_coef[1]  = a01;
        g_coef[2]  = a34;          g_coef[3]  = a314;
        g_coef[4]  = a37;          g_coef[5]  = a310;
        g_coef[6]  = a67;          g_coef[7]  = a617 * S6;
        g_coef[8]  = a610;         g_coef[9]  = a920 * S6;
        g_coef[10] = a910;         g_coef[11] = a164;
        g_coef[12] = a1614;        g_coef[13] = a197 * S36;
        g_coef[14] = a1917 * S216; g_coef[15] = a2210 * S36;
        g_coef[16] = a2220 * S216;
        g_raw[0] = a617; g_raw[1] = a920; g_raw[2] = a197;
        g_raw[3] = a1917; g_raw[4] = a2210; g_raw[5] = a2220;
        {
            float m = -1e30f;
            for (int i = 0; i < 24; i++) m = fmaxf(m, ik[i]);
            float e[24]; float s = 0.0f;
            for (int i = 0; i < 24; i++) { e[i] = expf(ik[i] - m); s += e[i]; }
            for (int i = 0; i < 24; i++) g_pi[i] = e[i] / s;
        }
    }
    for (int idx = tid; idx < 17 * 16; idx += blockDim.x) {
        int s = idx >> 4;
        int pq = idx & 15;
        const float* p = ew + s * 64 + pq * 4;
        float v0 = p[0], v1 = p[1], v2 = p[2], v3 = p[3];
        float m = fmaxf(fmaxf(v0, v1), fmaxf(v2, v3));
        float e0 = expf(v0 - m), e1 = expf(v1 - m), e2 = expf(v2 - m), e3 = expf(v3 - m);
        float ss = e0 + e1 + e2 + e3;
        int base = pq * 4;
        g_Bst[(base + 0) * 20 + s] = e0 / ss;
        g_Bst[(base + 1) * 20 + s] = e1 / ss;
        g_Bst[(base + 2) * 20 + s] = e2 / ss;
        g_Bst[(base + 3) * 20 + s] = e3 / ss;
    }
}

// ---------------------------------------------------------------------------
// Forward kernel
// ---------------------------------------------------------------------------
struct Coef {
    float a00, a01, a34, a314, a37, a310, a67, a617, a610,
          a920, a910, a164, a1614, a197, a1917, a2210, a2220;
};

struct ERow { float4 e0, e1, e2, e3; float e16; };

__device__ __forceinline__ ERow loadE(const float* __restrict__ Bsh, int ctx) {
    const float4* r = reinterpret_cast<const float4*>(Bsh + ctx * 20);
    ERow e;
    e.e0 = r[0]; e.e1 = r[1]; e.e2 = r[2]; e.e3 = r[3];
    e.e16 = Bsh[ctx * 20 + 16];
    return e;
}

__device__ __forceinline__ void stepE(const float (&s)[24], float (&d)[24],
                                      const ERow& e, const Coef& k) {
    float t0  = k.a00 * s[0];
    float t1  = k.a01 * s[0];
    float t4  = fmaf(k.a34,  s[3], k.a164 * s[16]);
    float t7  = fmaf(k.a37,  s[3], fmaf(k.a67,  s[6], k.a197 * s[19]));
    float t10 = fmaf(k.a310, s[3], fmaf(k.a610, s[6], fmaf(k.a910, s[9], k.a2210 * s[22])));
    float t13 = fmaf(0.5f, s[13], s[12]);
    float t14 = fmaf(k.a314, s[3], k.a1614 * s[16]);
    d[17] = fmaf(k.a617, s[6], k.a1917 * s[19]);
    d[20] = fmaf(k.a920, s[9], k.a2220 * s[22]);
    d[23] = fmaf(0.0833333333333333f, s[13], 0.166666666666667f * s[23]);
    d[18] = s[17]; d[19] = s[18]; d[21] = s[20]; d[22] = s[21];
    d[0]  = t0    * e.e0.x;  d[1]  = t1    * e.e0.y;
    d[2]  = s[1]  * e.e0.z;  d[3]  = s[2]  * e.e0.w;
    d[4]  = t4    * e.e1.x;  d[5]  = s[4]  * e.e1.y;
    d[6]  = s[5]  * e.e1.z;  d[7]  = t7    * e.e1.w;
    d[8]  = s[7]  * e.e2.x;  d[9]  = s[8]  * e.e2.y;
    d[10] = t10   * e.e2.z;  d[11] = s[10] * e.e2.w;
    d[12] = s[11] * e.e3.x;  d[13] = t13   * e.e3.y;
    d[14] = t14   * e.e3.z;  d[15] = s[14] * e.e3.w;
    d[16] = s[15] * e.e16;
}

__device__ __forceinline__ float sum24(const float (&a)[24]) {
    float s01 = (a[0] + a[1])   + (a[2] + a[3]);
    float s23 = (a[4] + a[5])   + (a[6] + a[7]);
    float s45 = (a[8] + a[9])   + (a[10] + a[11]);
    float s67 = (a[12] + a[13]) + (a[14] + a[15]);
    float s89 = (a[16] + a[17]) + (a[18] + a[19]);
    float sab = (a[20] + a[21]) + (a[22] + a[23]);
    return ((s01 + s23) + (s45 + s67)) + (s89 + sab);
}

__global__ __launch_bounds__(32, 1)
void forward_kernel(const int* __restrict__ seq, float* __restrict__ out) {
    __shared__ __align__(16) float Bsh[64 * 20];
    for (int i = threadIdx.x; i < 64 * 20; i += 32) Bsh[i] = g_Bst[i];
    __syncthreads();

    Coef k;
    k.a00   = g_coef[0];  k.a01   = g_coef[1];
    k.a34   = g_coef[2];  k.a314  = g_coef[3];
    k.a37   = g_coef[4];  k.a310  = g_coef[5];
    k.a67   = g_coef[6];  k.a617  = g_coef[7];
    k.a610  = g_coef[8];  k.a920  = g_coef[9];
    k.a910  = g_coef[10]; k.a164  = g_coef[11];
    k.a1614 = g_coef[12]; k.a197  = g_coef[13];
    k.a1917 = g_coef[14]; k.a2210 = g_coef[15];
    k.a2220 = g_coef[16];
    float r617 = g_raw[0], r920 = g_raw[1], r197 = g_raw[2],
          r1917 = g_raw[3], r2210 = g_raw[4], r2220 = g_raw[5];

    int b = blockIdx.x * 32 + threadIdx.x;
    const int4* q4 = reinterpret_cast<const int4*>(seq + b * T_LEN);

    float A[24], B[24];
    float P[24];
    #pragma unroll
    for (int i = 0; i < 24; i++) P[i] = g_pi[i];

    // t=1: pure transition step (raw coefs), then convert to beta scale.
    {
        float t0  = k.a00 * P[0];
        float t1  = k.a01 * P[0];
        float t4  = fmaf(k.a34,  P[3], k.a164 * P[16]);
        float t7  = fmaf(k.a37,  P[3], fmaf(k.a67,  P[6], r197 * P[19]));
        float t10 = fmaf(k.a310, P[3], fmaf(k.a610, P[6], fmaf(k.a910, P[9], r2210 * P[22])));
        float t13 = fmaf(0.5f, P[13], P[12]);
        float t14 = fmaf(k.a314, P[3], k.a1614 * P[16]);
        float t17 = fmaf(r617, P[6], r1917 * P[19]);
        float t20 = fmaf(r920, P[9], r2220 * P[22]);
        float t23 = fmaf(0.5f, P[13], P[23]);
        B[0] = t0;    B[1] = t1;    B[2] = P[1];  B[3] = P[2];
        B[4] = t4;    B[5] = P[4];  B[6] = P[5];  B[7] = t7;
        B[8] = P[7];  B[9] = P[8];  B[10] = t10;  B[11] = P[10];
        B[12] = P[11]; B[13] = t13; B[14] = t14;  B[15] = P[14];
        B[16] = P[15];
        B[17] = t17;
        B[18] = 6.0f  * P[17];
        B[19] = 36.0f * P[18];
        B[20] = t20;
        B[21] = 6.0f  * P[20];
        B[22] = 36.0f * P[21];
        B[23] = t23;
    }

    int4 v = q4[0];
    {
        int c2 = ((((v.x << 2) | v.y) << 2) | v.z) & 63;
        int c3 = ((c2 << 2) | v.w) & 63;
        ERow e2 = loadE(Bsh, c2), e3 = loadE(Bsh, c3);
        stepE(B, A, e2, k);   // t=2
        stepE(A, B, e3, k);   // t=3
    }
    int ctx = ((((v.y << 2) | v.z) << 2) | v.w) & 63;

    float loglik = -3.58351893845611f;   // 2*ln(1/6)

    // ---- Pipelined main loop: blocks 1..498 in ping-pong pairs, block 499 epilogue.
    ERow eA0, eA1, eA2, eA3;        // E rows for the block about to run
    ERow eB0, eB1, eB2, eB3;        // E rows for the following block
    {
        int4 u = q4[1];
        int c0 = ((ctx << 2) | u.x) & 63;
        int c1 = ((c0  << 2) | u.y) & 63;
        int c2 = ((c1  << 2) | u.z) & 63;
        int c3 = ((c2  << 2) | u.w) & 63;
        eA0 = loadE(Bsh, c0); eA1 = loadE(Bsh, c1);
        eA2 = loadE(Bsh, c2); eA3 = loadE(Bsh, c3);
        ctx = c3;
    }
    int4 un = q4[2];                 // seq for block 2

    for (int j = 1; j < 499; j += 2) {
        // ---- phase A: run block j with eA; load eB for block j+1 ----
        int4 up1 = q4[j + 2];        // seq for block j+2 (j+2 <= 499)
        {
            int n0 = ((ctx << 2) | un.x) & 63;
            int n1 = ((n0  << 2) | un.y) & 63;
            int n2 = ((n1  << 2) | un.z) & 63;
            int n3 = ((n2  << 2) | un.w) & 63;
            eB0 = loadE(Bsh, n0); eB1 = loadE(Bsh, n1);
            eB2 = loadE(Bsh, n2); eB3 = loadE(Bsh, n3);
            ctx = n3;
        }
        stepE(B, A, eA0, k);
        stepE(A, B, eA1, k);
        stepE(B, A, eA2, k);
        stepE(A, B, eA3, k);
        if ((j & 3) == 3) {
            float S = sum24(B);
            loglik += __logf(S);
            float inv = __fdividef(1.0f, S);
            #pragma unroll
            for (int i = 0; i < 24; i++) B[i] *= inv;
        }
        // ---- phase B: run block j+1 with eB; load eA for block j+2 ----
        int jn = (j + 3 < 500) ? j + 3 : 499;
        int4 up2 = q4[jn];           // seq for block j+3 (next pair's un)
        {
            int m0 = ((ctx << 2) | up1.x) & 63;
            int m1 = ((m0  << 2) | up1.y) & 63;
            int m2 = ((m1  << 2) | up1.z) & 63;
            int m3 = ((m2  << 2) | up1.w) & 63;
            eA0 = loadE(Bsh, m0); eA1 = loadE(Bsh, m1);
            eA2 = loadE(Bsh, m2); eA3 = loadE(Bsh, m3);
            ctx = m3;
        }
        stepE(B, A, eB0, k);
        stepE(A, B, eB1, k);
        stepE(B, A, eB2, k);
        stepE(A, B, eB3, k);
        // (j+1) is even: never a checkpoint boundary (checkpoints at j%4==3)
        un = up2;
    }

    // ---- epilogue: block 499 (eA loaded in last pair's phase B) ----
    stepE(B, A, eA0, k);
    stepE(A, B, eA1, k);
    stepE(B, A, eA2, k);
    stepE(A, B, eA3, k);
    {
        float S = sum24(B);
        loglik += __logf(S);
        float inv = __fdividef(1.0f, S);
        #pragma unroll
        for (int i = 0; i < 24; i++) B[i] *= inv;
    }

    // Final beta -> alpha mass correction: sum(beta_j / d_j).
    const float S6 = 1.0f / 6.0f, S36 = 1.0f / 36.0f;
    float Sf = (B[0] + B[1]) + (B[2] + B[3]) + (B[4] + B[5]) + (B[6] + B[7])
             + (B[8] + B[9]) + (B[10] + B[11]) + (B[12] + B[13]) + (B[14] + B[15])
             + (B[16] + B[17]) + (B[20] + B[23])
             + S6 * (B[18] + B[21]) + S36 * (B[19] + B[22]);
    loglik += __logf(Sf);

    out[b] = loglik;
}

// ---------------------------------------------------------------------------
// Launch
// ---------------------------------------------------------------------------
extern "C" void kernel_launch(void* const* d_in, const int* in_sizes, int n_in,
                              void* d_out, int out_size) {
    const float* transition_kernel = (const float*)d_in[0];
    const float* emission_kernel   = (const float*)d_in[1];
    const float* init_kernel       = (const float*)d_in[2];
    const int*   seq               = (const int*)d_in[3];
    float* out = (float*)d_out;

    setup_kernel<<<1, 256>>>(transition_kernel, emission_kernel, init_kernel);
    forward_kernel<<<BATCH / 32, 32>>>(seq, out);
}